// round 10
// baseline (speedup 1.0000x reference)
#include <cuda_runtime.h>

// Problem constants (fixed by reference setup_inputs)
#define BATCH    8
#define H        200
#define W        200
#define C        256
#define CROP     7
#define NROIS    512

#define C4       (C / 4)                       // 64 float4 per pixel
#define NPOS     (BATCH * NROIS * CROP * CROP) // 200704 output positions
#define POS_PER_WARP  2
#define WARPS_PER_BLOCK 8
#define POS_PER_BLOCK (POS_PER_WARP * WARPS_PER_BLOCK)   // 16

__device__ __forceinline__ float4 lerp2d(const float4 v00, const float4 v01,
                                         const float4 v10, const float4 v11,
                                         const float fx, const float fy)
{
    float4 r;
    float t, b;
    t = v00.x + (v01.x - v00.x) * fx;  b = v10.x + (v11.x - v10.x) * fx;  r.x = t + (b - t) * fy;
    t = v00.y + (v01.y - v00.y) * fx;  b = v10.y + (v11.y - v10.y) * fx;  r.y = t + (b - t) * fy;
    t = v00.z + (v01.z - v00.z) * fx;  b = v10.z + (v11.z - v10.z) * fx;  r.z = t + (b - t) * fy;
    t = v00.w + (v01.w - v00.w) * fx;  b = v10.w + (v11.w - v10.w) * fx;  r.w = t + (b - t) * fy;
    return r;
}

__device__ __forceinline__ void stcs4(float4* p, const float4 v)
{
    asm volatile("st.global.cs.v4.f32 [%0], {%1, %2, %3, %4};"
                 :: "l"(p), "f"(v.x), "f"(v.y), "f"(v.z), "f"(v.w) : "memory");
}

__device__ __forceinline__ float4 ldg4(const float4* p)
{
    float4 v;
    asm volatile("ld.global.nc.v4.f32 {%0, %1, %2, %3}, [%4];"
                 : "=f"(v.x), "=f"(v.y), "=f"(v.z), "=f"(v.w) : "l"(p));
    return v;
}

struct PosAddr {
    int p00, p01, p10, p11;
    float fx, fy;
};

__device__ __forceinline__ PosAddr decode(const float4* __restrict__ rois, int pos)
{
    const int pix = pos % (CROP * CROP);
    const int r   = pos / (CROP * CROP);
    const int iy  = pix / CROP;
    const int ix  = pix % CROP;
    const int b   = r >> 9;

    const float4 box = __ldg(&rois[r]);

    // Match reference math exactly:
    // ys = y1*(H-1) + i * ((y2-y1)*(H-1)/(crop-1))
    const float ys = box.x * (float)(H - 1)
                   + (float)iy * ((box.z - box.x) * (float)(H - 1) / (float)(CROP - 1));
    const float xs = box.y * (float)(W - 1)
                   + (float)ix * ((box.w - box.y) * (float)(W - 1) / (float)(CROP - 1));

    const float y0f = floorf(ys);
    const float x0f = floorf(xs);

    PosAddr a;
    a.fy = ys - y0f;
    a.fx = xs - x0f;

    int y0 = (int)y0f;  y0 = min(max(y0, 0), H - 1);
    int x0 = (int)x0f;  x0 = min(max(x0, 0), W - 1);
    const int y1i = min(y0 + 1, H - 1);
    const int x1i = min(x0 + 1, W - 1);

    const int row0 = (b * H + y0)  * W;
    const int row1 = (b * H + y1i) * W;
    a.p00 = (row0 + x0)  * C4;
    a.p01 = (row0 + x1i) * C4;
    a.p10 = (row1 + x0)  * C4;
    a.p11 = (row1 + x1i) * C4;
    return a;
}

__global__ __launch_bounds__(256, 2)
void roi_crop_resize_kernel(const float4* __restrict__ img,   // [B*H*W, 64] float4
                            const float4* __restrict__ rois,  // [4096] float4
                            float4* __restrict__ out)         // [NPOS, 64] float4
{
    const int tid  = threadIdx.x;
    const int lane = tid & 31;
    const int warp = tid >> 5;
    const int pos0 = blockIdx.x * POS_PER_BLOCK + warp * POS_PER_WARP;
    const int pos1 = pos0 + 1;

    const PosAddr A = decode(rois, pos0);
    const PosAddr B = decode(rois, pos1);

    const int ca = lane;        // float4 chunk 0..31 (bytes 0..511 of pixel)
    const int cb = lane + 32;   // float4 chunk 32..63 (bytes 512..1023)

    // 16 independent 128-bit loads, ordered as four 2KB LINEAR ADDRESS RUNS:
    // p00 and p01 are x-adjacent pixels in the same image row, so
    // (a00,b00,a01,b01) covers one contiguous 2KB region — maximal HBM
    // row-buffer locality per activation. Same for the bottom row.
    const float4 Aa00 = ldg4(&img[A.p00 + ca]);   // A top row: 2KB run
    const float4 Ab00 = ldg4(&img[A.p00 + cb]);
    const float4 Aa01 = ldg4(&img[A.p01 + ca]);
    const float4 Ab01 = ldg4(&img[A.p01 + cb]);
    const float4 Aa10 = ldg4(&img[A.p10 + ca]);   // A bottom row: 2KB run
    const float4 Ab10 = ldg4(&img[A.p10 + cb]);
    const float4 Aa11 = ldg4(&img[A.p11 + ca]);
    const float4 Ab11 = ldg4(&img[A.p11 + cb]);

    const float4 Ba00 = ldg4(&img[B.p00 + ca]);   // B top row: 2KB run
    const float4 Bb00 = ldg4(&img[B.p00 + cb]);
    const float4 Ba01 = ldg4(&img[B.p01 + ca]);
    const float4 Bb01 = ldg4(&img[B.p01 + cb]);
    const float4 Ba10 = ldg4(&img[B.p10 + ca]);   // B bottom row: 2KB run
    const float4 Bb10 = ldg4(&img[B.p10 + cb]);
    const float4 Ba11 = ldg4(&img[B.p11 + ca]);
    const float4 Bb11 = ldg4(&img[B.p11 + cb]);

    const float4 rA0 = lerp2d(Aa00, Aa01, Aa10, Aa11, A.fx, A.fy);
    const float4 rA1 = lerp2d(Ab00, Ab01, Ab10, Ab11, A.fx, A.fy);
    const float4 rB0 = lerp2d(Ba00, Ba01, Ba10, Ba11, B.fx, B.fy);
    const float4 rB1 = lerp2d(Bb00, Bb01, Bb10, Bb11, B.fx, B.fy);

    // One long 2KB write burst per warp, streaming (evict-first) stores.
    float4* o0 = (float4*)out + (size_t)pos0 * C4;
    float4* o1 = (float4*)out + (size_t)pos1 * C4;
    stcs4(o0 + ca, rA0);
    stcs4(o0 + cb, rA1);
    stcs4(o1 + ca, rB0);
    stcs4(o1 + cb, rB1);
}

extern "C" void kernel_launch(void* const* d_in, const int* in_sizes, int n_in,
                              void* d_out, int out_size)
{
    const float4* img  = (const float4*)d_in[0];   // [8,200,200,256] fp32
    const float4* rois = (const float4*)d_in[1];   // [8,512,4] fp32
    float4* out        = (float4*)d_out;           // [8,512,7,7,256] fp32

    const int blocks = NPOS / POS_PER_BLOCK;       // 200704 / 16 = 12544
    roi_crop_resize_kernel<<<blocks, 256>>>(img, rois, out);
}

// round 11
// speedup vs baseline: 1.0004x; 1.0004x over previous
#include <cuda_runtime.h>

// Problem constants (fixed by reference setup_inputs)
#define BATCH    8
#define H        200
#define W        200
#define C        256
#define CROP     7
#define NROIS    512

#define C4       (C / 4)                       // 64 float4 per pixel
#define NPOS     (BATCH * NROIS * CROP * CROP) // 200704 output positions
#define POS_PER_WARP  2
#define WARPS_PER_BLOCK 8
#define POS_PER_BLOCK (POS_PER_WARP * WARPS_PER_BLOCK)   // 16

__device__ __forceinline__ float4 lerp2d(const float4 v00, const float4 v01,
                                         const float4 v10, const float4 v11,
                                         const float fx, const float fy)
{
    float4 r;
    float t, b;
    t = v00.x + (v01.x - v00.x) * fx;  b = v10.x + (v11.x - v10.x) * fx;  r.x = t + (b - t) * fy;
    t = v00.y + (v01.y - v00.y) * fx;  b = v10.y + (v11.y - v10.y) * fx;  r.y = t + (b - t) * fy;
    t = v00.z + (v01.z - v00.z) * fx;  b = v10.z + (v11.z - v10.z) * fx;  r.z = t + (b - t) * fy;
    t = v00.w + (v01.w - v00.w) * fx;  b = v10.w + (v11.w - v10.w) * fx;  r.w = t + (b - t) * fy;
    return r;
}

__device__ __forceinline__ void stcs4(float4* p, const float4 v)
{
    // streaming store: evict-first in L2 so write-once output doesn't evict image lines
    asm volatile("st.global.cs.v4.f32 [%0], {%1, %2, %3, %4};"
                 :: "l"(p), "f"(v.x), "f"(v.y), "f"(v.z), "f"(v.w) : "memory");
}

__device__ __forceinline__ float4 ldg4(const float4* p)
{
    float4 v;
    asm volatile("ld.global.nc.v4.f32 {%0, %1, %2, %3}, [%4];"
                 : "=f"(v.x), "=f"(v.y), "=f"(v.z), "=f"(v.w) : "l"(p));
    return v;
}

struct PosAddr {
    int p00, p01, p10, p11;
    float fx, fy;
};

__device__ __forceinline__ PosAddr decode(const float4* __restrict__ rois, int pos)
{
    const int pix = pos % (CROP * CROP);
    const int r   = pos / (CROP * CROP);
    const int iy  = pix / CROP;
    const int ix  = pix % CROP;
    const int b   = r >> 9;

    const float4 box = __ldg(&rois[r]);

    // Match reference math exactly:
    // ys = y1*(H-1) + i * ((y2-y1)*(H-1)/(crop-1))
    const float ys = box.x * (float)(H - 1)
                   + (float)iy * ((box.z - box.x) * (float)(H - 1) / (float)(CROP - 1));
    const float xs = box.y * (float)(W - 1)
                   + (float)ix * ((box.w - box.y) * (float)(W - 1) / (float)(CROP - 1));

    const float y0f = floorf(ys);
    const float x0f = floorf(xs);

    PosAddr a;
    a.fy = ys - y0f;
    a.fx = xs - x0f;

    int y0 = (int)y0f;  y0 = min(max(y0, 0), H - 1);
    int x0 = (int)x0f;  x0 = min(max(x0, 0), W - 1);
    const int y1i = min(y0 + 1, H - 1);
    const int x1i = min(x0 + 1, W - 1);

    const int row0 = (b * H + y0)  * W;
    const int row1 = (b * H + y1i) * W;
    a.p00 = (row0 + x0)  * C4;
    a.p01 = (row0 + x1i) * C4;
    a.p10 = (row1 + x0)  * C4;
    a.p11 = (row1 + x1i) * C4;
    return a;
}

__global__ __launch_bounds__(256, 2)
void roi_crop_resize_kernel(const float4* __restrict__ img,   // [B*H*W, 64] float4
                            const float4* __restrict__ rois,  // [4096] float4
                            float4* __restrict__ out)         // [NPOS, 64] float4
{
    const int tid  = threadIdx.x;
    const int lane = tid & 31;
    const int warp = tid >> 5;
    const int pos0 = blockIdx.x * POS_PER_BLOCK + warp * POS_PER_WARP;
    const int pos1 = pos0 + 1;

    const PosAddr A = decode(rois, pos0);
    const PosAddr B = decode(rois, pos1);

    const int ca = lane;        // float4 chunk 0..31
    const int cb = lane + 32;   // float4 chunk 32..63

    // 16 independent 128-bit loads in flight: one long 8KB read burst per warp,
    // no barriers, no loop-carried deps — measured optimum across the full
    // MLP/occupancy/ordering/staging sweep (rounds 1-10).
    const float4 Aa00 = ldg4(&img[A.p00 + ca]);
    const float4 Aa01 = ldg4(&img[A.p01 + ca]);
    const float4 Aa10 = ldg4(&img[A.p10 + ca]);
    const float4 Aa11 = ldg4(&img[A.p11 + ca]);
    const float4 Ab00 = ldg4(&img[A.p00 + cb]);
    const float4 Ab01 = ldg4(&img[A.p01 + cb]);
    const float4 Ab10 = ldg4(&img[A.p10 + cb]);
    const float4 Ab11 = ldg4(&img[A.p11 + cb]);

    const float4 Ba00 = ldg4(&img[B.p00 + ca]);
    const float4 Ba01 = ldg4(&img[B.p01 + ca]);
    const float4 Ba10 = ldg4(&img[B.p10 + ca]);
    const float4 Ba11 = ldg4(&img[B.p11 + ca]);
    const float4 Bb00 = ldg4(&img[B.p00 + cb]);
    const float4 Bb01 = ldg4(&img[B.p01 + cb]);
    const float4 Bb10 = ldg4(&img[B.p10 + cb]);
    const float4 Bb11 = ldg4(&img[B.p11 + cb]);

    const float4 rA0 = lerp2d(Aa00, Aa01, Aa10, Aa11, A.fx, A.fy);
    const float4 rA1 = lerp2d(Ab00, Ab01, Ab10, Ab11, A.fx, A.fy);
    const float4 rB0 = lerp2d(Ba00, Ba01, Ba10, Ba11, B.fx, B.fy);
    const float4 rB1 = lerp2d(Bb00, Bb01, Bb10, Bb11, B.fx, B.fy);

    // One long 2KB write burst per warp, streaming (evict-first) stores.
    float4* o0 = (float4*)out + (size_t)pos0 * C4;
    float4* o1 = (float4*)out + (size_t)pos1 * C4;
    stcs4(o0 + ca, rA0);
    stcs4(o0 + cb, rA1);
    stcs4(o1 + ca, rB0);
    stcs4(o1 + cb, rB1);
}

extern "C" void kernel_launch(void* const* d_in, const int* in_sizes, int n_in,
                              void* d_out, int out_size)
{
    const float4* img  = (const float4*)d_in[0];   // [8,200,200,256] fp32
    const float4* rois = (const float4*)d_in[1];   // [8,512,4] fp32
    float4* out        = (float4*)d_out;           // [8,512,7,7,256] fp32

    const int blocks = NPOS / POS_PER_BLOCK;       // 200704 / 16 = 12544
    roi_crop_resize_kernel<<<blocks, 256>>>(img, rois, out);
}

// round 12
// speedup vs baseline: 1.0259x; 1.0255x over previous
#include <cuda_runtime.h>

// Problem constants (fixed by reference setup_inputs)
#define BATCH    8
#define H        200
#define W        200
#define C        256
#define CROP     7
#define NROIS    512

#define NPOS     (BATCH * NROIS * CROP * CROP) // 200704 output positions
#define POS_PER_WARP  2
#define WARPS_PER_BLOCK 8
#define POS_PER_BLOCK (POS_PER_WARP * WARPS_PER_BLOCK)   // 16

// 256-bit vector of 8 floats: lane owns channels [8*lane, 8*lane+8)
struct F8 { float v[8]; };

__device__ __forceinline__ F8 ldg8(const float* p)
{
    F8 r;
    asm volatile("ld.global.nc.v8.f32 {%0,%1,%2,%3,%4,%5,%6,%7}, [%8];"
                 : "=f"(r.v[0]), "=f"(r.v[1]), "=f"(r.v[2]), "=f"(r.v[3]),
                   "=f"(r.v[4]), "=f"(r.v[5]), "=f"(r.v[6]), "=f"(r.v[7])
                 : "l"(p));
    return r;
}

__device__ __forceinline__ void stcs8(float* p, const F8 r)
{
    asm volatile("st.global.cs.v8.f32 [%0], {%1,%2,%3,%4,%5,%6,%7,%8};"
                 :: "l"(p),
                    "f"(r.v[0]), "f"(r.v[1]), "f"(r.v[2]), "f"(r.v[3]),
                    "f"(r.v[4]), "f"(r.v[5]), "f"(r.v[6]), "f"(r.v[7])
                 : "memory");
}

__device__ __forceinline__ F8 lerp2d8(const F8 v00, const F8 v01,
                                      const F8 v10, const F8 v11,
                                      const float fx, const float fy)
{
    F8 r;
    #pragma unroll
    for (int i = 0; i < 8; i++) {
        const float t = v00.v[i] + (v01.v[i] - v00.v[i]) * fx;
        const float b = v10.v[i] + (v11.v[i] - v10.v[i]) * fx;
        r.v[i] = t + (b - t) * fy;
    }
    return r;
}

struct PosAddr {
    int p00, p01, p10, p11;   // pixel base indices in floats (pixel# * 256)
    float fx, fy;
};

__device__ __forceinline__ PosAddr decode(const float4* __restrict__ rois, int pos)
{
    const int pix = pos % (CROP * CROP);
    const int r   = pos / (CROP * CROP);
    const int iy  = pix / CROP;
    const int ix  = pix % CROP;
    const int b   = r >> 9;

    const float4 box = __ldg(&rois[r]);

    // Match reference math exactly:
    // ys = y1*(H-1) + i * ((y2-y1)*(H-1)/(crop-1))
    const float ys = box.x * (float)(H - 1)
                   + (float)iy * ((box.z - box.x) * (float)(H - 1) / (float)(CROP - 1));
    const float xs = box.y * (float)(W - 1)
                   + (float)ix * ((box.w - box.y) * (float)(W - 1) / (float)(CROP - 1));

    const float y0f = floorf(ys);
    const float x0f = floorf(xs);

    PosAddr a;
    a.fy = ys - y0f;
    a.fx = xs - x0f;

    int y0 = (int)y0f;  y0 = min(max(y0, 0), H - 1);
    int x0 = (int)x0f;  x0 = min(max(x0, 0), W - 1);
    const int y1i = min(y0 + 1, H - 1);
    const int x1i = min(x0 + 1, W - 1);

    const int row0 = (b * H + y0)  * W;
    const int row1 = (b * H + y1i) * W;
    a.p00 = (row0 + x0)  * C;
    a.p01 = (row0 + x1i) * C;
    a.p10 = (row1 + x0)  * C;
    a.p11 = (row1 + x1i) * C;
    return a;
}

__global__ __launch_bounds__(256, 2)
void roi_crop_resize_kernel(const float* __restrict__ img,    // [B*H*W*256] fp32
                            const float4* __restrict__ rois,  // [4096] float4
                            float* __restrict__ out)          // [NPOS*256] fp32
{
    const int tid  = threadIdx.x;
    const int lane = tid & 31;
    const int warp = tid >> 5;
    const int pos0 = blockIdx.x * POS_PER_BLOCK + warp * POS_PER_WARP;
    const int pos1 = pos0 + 1;

    const PosAddr A = decode(rois, pos0);
    const PosAddr B = decode(rois, pos1);

    const int co = lane * 8;   // this lane's channel offset within the 256-ch pixel

    // 8 independent 256-bit loads in flight: each instruction is one warp-wide
    // 1KB contiguous access = exactly one pixel. Same 8KB read burst per warp
    // as the LDG.128 best kernel, but half the requests at 2x the granule.
    const F8 Aa00 = ldg8(img + A.p00 + co);
    const F8 Aa01 = ldg8(img + A.p01 + co);
    const F8 Aa10 = ldg8(img + A.p10 + co);
    const F8 Aa11 = ldg8(img + A.p11 + co);

    const F8 Ba00 = ldg8(img + B.p00 + co);
    const F8 Ba01 = ldg8(img + B.p01 + co);
    const F8 Ba10 = ldg8(img + B.p10 + co);
    const F8 Ba11 = ldg8(img + B.p11 + co);

    const F8 rA = lerp2d8(Aa00, Aa01, Aa10, Aa11, A.fx, A.fy);
    const F8 rB = lerp2d8(Ba00, Ba01, Ba10, Ba11, B.fx, B.fy);

    // Two warp-wide 1KB streaming stores.
    stcs8(out + (size_t)pos0 * C + co, rA);
    stcs8(out + (size_t)pos1 * C + co, rB);
}

extern "C" void kernel_launch(void* const* d_in, const int* in_sizes, int n_in,
                              void* d_out, int out_size)
{
    const float*  img  = (const float*)d_in[0];    // [8,200,200,256] fp32
    const float4* rois = (const float4*)d_in[1];   // [8,512,4] fp32
    float* out         = (float*)d_out;            // [8,512,7,7,256] fp32

    const int blocks = NPOS / POS_PER_BLOCK;       // 200704 / 16 = 12544
    roi_crop_resize_kernel<<<blocks, 256>>>(img, rois, out);
}